// round 12
// baseline (speedup 1.0000x reference)
#include <cuda_runtime.h>
#include <math.h>

#define BATCH 512
#define LSEQ  100
#define NINPUT 3
#define HDIM  256
#define G3    768
#define DSH   10
#define WINW  5
#define MSEQ  95          // LSEQ - WINW
#define TBR   8           // batch samples per recurrent CTA

#define BL    (BATCH*LSEQ)      // 51200
#define BM95  (BATCH*MSEQ)      // 48640

typedef unsigned long long u64;
typedef unsigned short u16;

// ---------------- scratch (static device memory; no allocations) ----------
__device__ float  g_xw1 [2*BL*G3];          // layer-1 gate inputs, per GRU
__device__ float  g_h1  [2*BL*HDIM];        // layer-0 outputs
__device__ float  g_out [2*BL*HDIM];        // layer-1 outputs (out1/out2)
__device__ float  g_q   [2*BL];
__device__ float  g_e   [2*BL];
__device__ float  g_cat [2*BM95*2*HDIM];    // [c, out_shift] concat for FC
__device__ float  g_fused[2*BM95*HDIM];     // FC output
__device__ u16    g_wB  [4*G3*HDIM];        // Whh bf16, [slot][g=768][k=256]
// slots: 0=r1_Whh0 1=r2_Whh0 2=r1_Whh1 3=r2_Whh1

__device__ __forceinline__ float sigf(float x) { return 1.f / (1.f + __expf(-x)); }

// round-to-nearest-even fp32 -> bf16 bits
__device__ __forceinline__ unsigned bfr(float f) {
    unsigned u = __float_as_uint(f);
    return (u + 0x7FFFu + ((u >> 16) & 1u)) >> 16;
}
__device__ __forceinline__ unsigned pack_bf(float lo, float hi) {
    unsigned r; asm("cvt.rn.bf16x2.f32 %0, %1, %2;" : "=r"(r) : "f"(hi), "f"(lo));
    return r;
}

#define CPA(dst, src) \
    asm volatile("cp.async.cg.shared.global [%0], [%1], 16;" :: "r"(dst), "l"(src))
#define CPC() asm volatile("cp.async.commit_group;" ::: "memory")

#define LDMX4(r0,r1,r2,r3,ad) \
    asm volatile("ldmatrix.sync.aligned.m8n8.x4.shared.b16 {%0,%1,%2,%3}, [%4];" \
        : "=r"(r0),"=r"(r1),"=r"(r2),"=r"(r3) : "r"(ad))
#define LDMX2(r0,r1,ad) \
    asm volatile("ldmatrix.sync.aligned.m8n8.x2.shared.b16 {%0,%1}, [%2];" \
        : "=r"(r0),"=r"(r1) : "r"(ad))
#define MMA16816(acc,a,b0v,b1v) \
    asm volatile("mma.sync.aligned.m16n8k16.row.col.f32.bf16.bf16.f32 " \
        "{%0,%1,%2,%3}, {%4,%5,%6,%7}, {%8,%9}, {%0,%1,%2,%3};" \
        : "+f"(acc[0]),"+f"(acc[1]),"+f"(acc[2]),"+f"(acc[3]) \
        : "r"(a[0]),"r"(a[1]),"r"(a[2]),"r"(a[3]),"r"(b0v),"r"(b1v))

// ---------------- weight prep: Whh fp32 -> bf16 (same layout) --------------
__global__ void k_prep(const float* __restrict__ w0, const float* __restrict__ w1,
                       const float* __restrict__ w2, const float* __restrict__ w3)
{
    int idx = blockIdx.x * blockDim.x + threadIdx.x;
    if (idx >= 4 * G3 * HDIM) return;
    int m = idx / (G3 * HDIM);
    int rem = idx % (G3 * HDIM);
    const float* W = (m == 0) ? w0 : (m == 1) ? w1 : (m == 2) ? w2 : w3;
    g_wB[idx] = (u16)bfr(W[rem]);
}

// ---------------- GRU recurrence via mma.sync (pipelined v2) ---------------
// 256 threads, 8 warps, TB=8 (M padded to 16 with zero rows).
// gates[8,768] = h[8,256] @ Whh^T per step; h split hi/lo bf16 (Markidis A).
// W bf16 streamed in a CYCLIC 3-buffer pipeline (prefetch distance 2,
// ONE barrier per chunk); stream never drains across step boundaries.
#define KCH   32
#define NCHK  8
#define WSTR  40      // halves per W-stage row (32 + 8 pad)
#define ASTR  264     // halves per A-stage row (256 + 8 pad)
#define GSTR  776     // floats per gates row (768 + 8 pad)
// SMEM map (bytes):
//     0: hA_hi [16][ASTR] halves   = 8448
//  8448: hA_lo [16][ASTR] halves   = 8448
// 16896: gates [8][GSTR] fp32      = 24832
// 41728: xs2   [8][4] fp32         = 128
// 41856: Wbuf x3 [768][WSTR] halves = 3*61440
#define REC_SMEM 226176

template<int FUSE>
__global__ void __launch_bounds__(256, 1)
k_rec_mma(const float* __restrict__ xw_base, const float* __restrict__ xin,
          const float* __restrict__ Wih_0, const float* __restrict__ Wih_1,
          const float* __restrict__ bih_0, const float* __restrict__ bih_1,
          int wslot,
          const float* __restrict__ bhh_0, const float* __restrict__ bhh_1,
          float* __restrict__ hout_base)
{
    extern __shared__ __align__(16) char dsm[];
    unsigned sb;
    asm("{ .reg .u64 t; cvta.to.shared.u64 t, %1; cvt.u32.u64 %0, t; }"
        : "=r"(sb) : "l"(dsm));
    unsigned sAhi = sb;
    unsigned sAlo = sb + 8448;
    unsigned sG   = sb + 16896;
    unsigned sW[3] = { sb + 41856, sb + 41856 + 61440, sb + 41856 + 122880 };
    float* xs2 = (float*)(dsm + 41728);

    int r   = blockIdx.y;
    int tid = threadIdx.x;
    int wid = tid >> 5, lane = tid & 31;
    int j   = tid;                       // hidden column for pointwise
    int b0  = blockIdx.x * TBR;
    const u16*   wbf  = g_wB + (size_t)(wslot + r) * (G3 * HDIM);
    const float* bhh  = r ? bhh_1 : bhh_0;
    const float* xw   = xw_base ? (xw_base + (size_t)r * BL * G3) : (const float*)0;
    float*       hout = hout_base + (size_t)r * BL * HDIM;

    // zero hA_hi, hA_lo (bytes 0..16896 = 4224 words)
    for (int idx = tid; idx < 4224; idx += 256) ((unsigned*)dsm)[idx] = 0;

    // fused input-projection weights (layer 0)
    float wx[9], bx[3];
    if (FUSE) {
        const float* Wih = r ? Wih_1 : Wih_0;
        const float* bih = r ? bih_1 : bih_0;
#pragma unroll
        for (int g = 0; g < 3; g++) {
            wx[g*3+0] = Wih[(j + g*HDIM)*3 + 0];
            wx[g*3+1] = Wih[(j + g*HDIM)*3 + 1];
            wx[g*3+2] = Wih[(j + g*HDIM)*3 + 2];
            bx[g]     = bih[j + g*HDIM];
        }
    }
    float bhr = bhh[j], bhz = bhh[j + HDIM], bhn = bhh[j + 2*HDIM];

    // h_prev lives in registers (thread j owns column j, 8 rows)
    float hp[TBR];
#pragma unroll
    for (int i = 0; i < TBR; i++) hp[i] = 0.f;

    // layer-1 gate-input pipeline registers
    float xg[24];
    if (!FUSE) {
#pragma unroll
        for (int i = 0; i < TBR; i++) {
            size_t base = ((size_t)(b0 + i) * LSEQ + 0) * G3;
            xg[i*3+0] = xw[base + j];
            xg[i*3+1] = xw[base + HDIM + j];
            xg[i*3+2] = xw[base + 2*HDIM + j];
        }
    }

    float acc[12][4];
#pragma unroll
    for (int t12 = 0; t12 < 12; t12++)
#pragma unroll
        for (int q = 0; q < 4; q++) acc[t12][q] = 0.f;

    // prologue: issue chunks 0 (buf0) and 1 (buf1)
#pragma unroll
    for (int p = 0; p < 2; p++) {
#pragma unroll
        for (int i = 0; i < 12; i++) {
            int cidx = tid + i * 256;
            int row = cidx >> 2, kq = cidx & 3;
            CPA(sW[p] + 2u*(row*WSTR + kq*8), wbf + row*HDIM + p*KCH + kq*8);
        }
        CPC();
    }
    __syncthreads();   // hA zero-init visible

    int cg = 0;        // global chunk counter; chunk = cg&7, buf = cg%3
    for (int t = 0; t < LSEQ; t++) {
        if (FUSE && tid < TBR * 3)
            xs2[(tid/3)*4 + (tid%3)] =
                xin[((size_t)(b0 + tid/3) * LSEQ + t) * NINPUT + (tid%3)];

#pragma unroll
        for (int c = 0; c < NCHK; c++) {
            // own copies for chunk cg done (outstanding: cg, cg+1)
            asm volatile("cp.async.wait_group 1;" ::: "memory");
            __syncthreads();  // everyone's chunk-cg copies landed; compute cg-1 done
            // issue prefetch for chunk cg+2 (writes buf (cg+2)%3, safe now)
            {
                int koff = ((cg + 2) & 7) * KCH;
                unsigned nbuf = sW[(cg + 2) % 3];
#pragma unroll
                for (int i = 0; i < 12; i++) {
                    int cidx = tid + i * 256;
                    int row = cidx >> 2, kq = cidx & 3;
                    CPA(nbuf + 2u*(row*WSTR + kq*8), wbf + row*HDIM + koff + kq*8);
                }
                CPC();
            }
            // compute chunk cg
            unsigned ahi[2][4], alo[2][4];
#pragma unroll
            for (int ks = 0; ks < 2; ks++) {
                unsigned colo = 2u*((lane & 15)*ASTR + c*KCH + ks*16 + (lane>>4)*8);
                LDMX4(ahi[ks][0], ahi[ks][1], ahi[ks][2], ahi[ks][3], sAhi + colo);
                LDMX4(alo[ks][0], alo[ks][1], alo[ks][2], alo[ks][3], sAlo + colo);
            }
            unsigned bufu = sW[cg % 3];
#pragma unroll
            for (int t12 = 0; t12 < 12; t12++) {
                int n0 = wid * 96 + t12 * 8;
#pragma unroll
                for (int ks = 0; ks < 2; ks++) {
                    unsigned bd = bufu + 2u*((n0 + (lane & 7))*WSTR
                                             + ks*16 + ((lane>>3)&1)*8);
                    unsigned bf0, bf1;
                    LDMX2(bf0, bf1, bd);
                    MMA16816(acc[t12], ahi[ks], bf0, bf1);
                    MMA16816(acc[t12], alo[ks], bf0, bf1);
                }
            }
            cg++;
        }

        // gates epilogue: rows 0-7 live in c0,c1 (row = lane>>2)
        {
            int grow = lane >> 2;
            int gcol = (lane & 3) * 2;
#pragma unroll
            for (int t12 = 0; t12 < 12; t12++) {
                int n0 = wid * 96 + t12 * 8;
                unsigned gad = sG + 4u*(grow*GSTR + n0 + gcol);
                asm volatile("st.shared.v2.f32 [%0], {%1, %2};"
                             :: "r"(gad), "f"(acc[t12][0]), "f"(acc[t12][1])
                             : "memory");
                acc[t12][0] = 0.f; acc[t12][1] = 0.f;
                acc[t12][2] = 0.f; acc[t12][3] = 0.f;
            }
        }
        __syncthreads();

        // pointwise GRU update: thread j handles column j for 8 rows
        const float* gp = (const float*)(dsm + 16896);
#pragma unroll
        for (int i = 0; i < TBR; i++) {
            float gxr, gxz, gxn;
            if (FUSE) {
                float x0 = xs2[i*4+0], x1 = xs2[i*4+1], x2 = xs2[i*4+2];
                gxr = bx[0] + x0*wx[0] + x1*wx[1] + x2*wx[2];
                gxz = bx[1] + x0*wx[3] + x1*wx[4] + x2*wx[5];
                gxn = bx[2] + x0*wx[6] + x1*wx[7] + x2*wx[8];
            } else {
                gxr = xg[i*3+0]; gxz = xg[i*3+1]; gxn = xg[i*3+2];
            }
            float sr = gp[i*GSTR + j];
            float sz = gp[i*GSTR + HDIM + j];
            float sn = gp[i*GSTR + 2*HDIM + j];
            float rg = sigf(gxr + sr + bhr);
            float zg = sigf(gxz + sz + bhz);
            float ng = tanhf(gxn + rg * (sn + bhn));
            float hn = (1.f - zg) * ng + zg * hp[i];
            hp[i] = hn;
            unsigned hb = bfr(hn);
            float back = __uint_as_float(hb << 16);
            unsigned lb = bfr(hn - back);
            unsigned aoff = 2u*(i*ASTR + j);
            asm volatile("st.shared.b16 [%0], %1;" :: "r"(sAhi + aoff), "h"((u16)hb) : "memory");
            asm volatile("st.shared.b16 [%0], %1;" :: "r"(sAlo + aoff), "h"((u16)lb) : "memory");
            hout[((size_t)(b0 + i) * LSEQ + t) * HDIM + j] = hn;
        }
        if (!FUSE && t + 1 < LSEQ) {
#pragma unroll
            for (int i = 0; i < TBR; i++) {
                size_t base = ((size_t)(b0 + i) * LSEQ + (t+1)) * G3;
                xg[i*3+0] = xw[base + j];
                xg[i*3+1] = xw[base + HDIM + j];
                xg[i*3+2] = xw[base + 2*HDIM + j];
            }
        }
        // next chunk's barrier orders hA writes before compute reads
    }
}

// ==================== Markidis bf16 GEMM (3-mma, ~fp32 accuracy) ============
// C[M,Ntot] = A[M,K] @ B[Ntot,K]^T + bias.
// CTA tile 128M x 128N, BK=64, 8 warps (4m x 2n), hi/lo split on A and B.
#define LDSTR 72
#define MM_SMEM (4 * 128 * LDSTR * 2)   // Ahi, Alo, Bhi, Blo

__global__ void __launch_bounds__(256, 2)
k_mma(const float* __restrict__ A, size_t strideAz,
      const float* __restrict__ B0, const float* __restrict__ B1,
      const float* __restrict__ bias0, const float* __restrict__ bias1,
      float* __restrict__ C, size_t strideCz, int Ntot, int K)
{
    extern __shared__ __align__(16) char smm[];
    unsigned sb;
    asm("{ .reg .u64 t; cvta.to.shared.u64 t, %1; cvt.u32.u64 %0, t; }"
        : "=r"(sb) : "l"(smm));
    unsigned sAhi = sb;
    unsigned sAlo = sb + 128*LDSTR*2;
    unsigned sBhi = sb + 2*128*LDSTR*2;
    unsigned sBlo = sb + 3*128*LDSTR*2;

    int z = blockIdx.z;
    const float* Az   = A + (size_t)z * strideAz;
    const float* Bw   = z ? B1 : B0;
    const float* bias = z ? bias1 : bias0;
    float*       Cz   = C + (size_t)z * strideCz;

    int tid = threadIdx.x;
    int wid = tid >> 5, lane = tid & 31;
    int wm = wid & 3, wn = wid >> 2;
    int bm = blockIdx.y * 128, bn = blockIdx.x * 128;

    float acc[2][8][4];
#pragma unroll
    for (int mt = 0; mt < 2; mt++)
#pragma unroll
        for (int nt = 0; nt < 8; nt++)
#pragma unroll
            for (int q = 0; q < 4; q++) acc[mt][nt][q] = 0.f;

    int lrow = tid >> 1, lh = tid & 1;

    for (int kc = 0; kc < K; kc += 64) {
        __syncthreads();
#pragma unroll
        for (int s = 0; s < 2; s++) {   // s=0: A, s=1: B
            const float* src = s ? Bw : Az;
            int gr = s ? bn : bm;
            unsigned dhi = s ? sBhi : sAhi;
            unsigned dlo = s ? sBlo : sAlo;
#pragma unroll
            for (int i = 0; i < 8; i++) {
                float4 v = *(const float4*)&src[(size_t)(gr + lrow) * K + kc + lh*32 + i*4];
                unsigned hi0 = pack_bf(v.x, v.y), hi1 = pack_bf(v.z, v.w);
                float bxx = __uint_as_float((hi0 & 0xFFFFu) << 16);
                float bxy = __uint_as_float(hi0 & 0xFFFF0000u);
                float bxz = __uint_as_float((hi1 & 0xFFFFu) << 16);
                float bxw = __uint_as_float(hi1 & 0xFFFF0000u);
                unsigned lo0 = pack_bf(v.x - bxx, v.y - bxy);
                unsigned lo1 = pack_bf(v.z - bxz, v.w - bxw);
                unsigned off = 2u*(lrow*LDSTR + lh*32 + i*4);
                u64 ph, pl;
                asm("mov.b64 %0, {%1, %2};" : "=l"(ph) : "r"(hi0), "r"(hi1));
                asm("mov.b64 %0, {%1, %2};" : "=l"(pl) : "r"(lo0), "r"(lo1));
                asm volatile("st.shared.b64 [%0], %1;" :: "r"(dhi + off), "l"(ph) : "memory");
                asm volatile("st.shared.b64 [%0], %1;" :: "r"(dlo + off), "l"(pl) : "memory");
            }
        }
        __syncthreads();

#pragma unroll
        for (int ks = 0; ks < 4; ks++) {
            unsigned ahi[2][4], alo[2][4];
#pragma unroll
            for (int mt = 0; mt < 2; mt++) {
                unsigned colo = 2u*((wm*32 + mt*16 + (lane & 15))*LDSTR
                                    + ks*16 + (lane>>4)*8);
                LDMX4(ahi[mt][0], ahi[mt][1], ahi[mt][2], ahi[mt][3], sAhi + colo);
                LDMX4(alo[mt][0], alo[mt][1], alo[mt][2], alo[mt][3], sAlo + colo);
            }
#pragma unroll
            for (int nt = 0; nt < 8; nt++) {
                unsigned boff = 2u*((wn*64 + nt*8 + (lane & 7))*LDSTR
                                    + ks*16 + ((lane>>3)&1)*8);
                unsigned bh0, bh1, bl0, bl1;
                LDMX2(bh0, bh1, sBhi + boff);
                LDMX2(bl0, bl1, sBlo + boff);
#pragma unroll
                for (int mt = 0; mt < 2; mt++) {
                    MMA16816(acc[mt][nt], ahi[mt], bh0, bh1);   // hi*hi
                    MMA16816(acc[mt][nt], ahi[mt], bl0, bl1);   // hi*lo
                    MMA16816(acc[mt][nt], alo[mt], bh0, bh1);   // lo*hi
                }
            }
        }
    }

    int row0 = bm + wm*32;
    int col0 = bn + wn*64;
#pragma unroll
    for (int mt = 0; mt < 2; mt++) {
        int r0 = row0 + mt*16 + (lane >> 2);
#pragma unroll
        for (int nt = 0; nt < 8; nt++) {
            int c = col0 + nt*8 + (lane & 3) * 2;
            float b0v = bias[c], b1v = bias[c + 1];
            float2 v0 = make_float2(acc[mt][nt][0] + b0v, acc[mt][nt][1] + b1v);
            float2 v1 = make_float2(acc[mt][nt][2] + b0v, acc[mt][nt][3] + b1v);
            *(float2*)&Cz[(size_t)r0 * Ntot + c]       = v0;
            *(float2*)&Cz[(size_t)(r0 + 8) * Ntot + c] = v1;
        }
    }
}

// ---------------- q = out@aw[:H], e = out@aw[H:] (warp per (b,l)) ----------
__global__ void k_qe(const float* __restrict__ attn_w)
{
    int r    = blockIdx.y;
    int w    = blockIdx.x * 8 + (threadIdx.x >> 5);
    int lane = threadIdx.x & 31;
    const float* o = g_out + ((size_t)r * BL + w) * HDIM;
    float q = 0.f, e = 0.f;
#pragma unroll
    for (int h = lane * 8; h < lane * 8 + 8; h += 4) {
        float4 ov = *(const float4*)&o[h];
        float4 a1 = *(const float4*)&attn_w[h];
        float4 a2 = *(const float4*)&attn_w[HDIM + h];
        q += ov.x*a1.x + ov.y*a1.y + ov.z*a1.z + ov.w*a1.w;
        e += ov.x*a2.x + ov.y*a2.y + ov.z*a2.z + ov.w*a2.w;
    }
#pragma unroll
    for (int off = 16; off; off >>= 1) {
        q += __shfl_down_sync(0xffffffffu, q, off);
        e += __shfl_down_sync(0xffffffffu, e, off);
    }
    if (lane == 0) { g_q[r * BL + w] = q; g_e[r * BL + w] = e; }
}

// ---------------- windowed attention + concat for FC ----------------------
__global__ void k_attn()
{
    int r    = blockIdx.y;
    int bl95 = blockIdx.x;
    int b    = bl95 / MSEQ, l = bl95 % MSEQ;
    int h    = threadIdx.x;

    const float* qrow = g_q + r * BL + b * LSEQ;
    const float* erow = g_e + r * BL + b * LSEQ;
    float qv = qrow[l + WINW];
    float s[WINW];
    float mx = -1e30f;
#pragma unroll
    for (int k = 0; k < WINW; k++) { s[k] = qv + erow[l + k]; mx = fmaxf(mx, s[k]); }
    float sum = 0.f;
#pragma unroll
    for (int k = 0; k < WINW; k++) { s[k] = __expf(s[k] - mx); sum += s[k]; }
    float inv = 1.f / sum;

    const float* o = g_out + ((size_t)r * BL + b * LSEQ + l) * HDIM;
    float c = 0.f;
#pragma unroll
    for (int k = 0; k < WINW; k++) c += s[k] * inv * o[k * HDIM + h];

    size_t m = (size_t)r * BM95 + bl95;
    g_cat[m * (2*HDIM) + h]        = c;
    g_cat[m * (2*HDIM) + HDIM + h] = o[WINW * HDIM + h];
}

// ---------------- final head: concat(rnn1[b,l], rnn2[b,min(l+D,99)]) ------
__global__ void k_final(const float* __restrict__ outW, const float* __restrict__ outb,
                        float* __restrict__ out)
{
    int w    = blockIdx.x * 8 + (threadIdx.x >> 5);
    int lane = threadIdx.x & 31;
    int b = w / LSEQ, l = w % LSEQ;

    const float* A1 = (l < WINW)
        ? (g_out   + ((size_t)(b * LSEQ + l)) * HDIM)
        : (g_fused + ((size_t)(b * MSEQ + l - WINW)) * HDIM);
    int lidx = min(l + DSH, LSEQ - 1);
    const float* A2 = (lidx < WINW)
        ? (g_out   + ((size_t)BL + b * LSEQ + lidx) * HDIM)
        : (g_fused + ((size_t)BM95 + b * MSEQ + lidx - WINW) * HDIM);

    float acc = 0.f;
#pragma unroll
    for (int h = lane * 8; h < lane * 8 + 8; h += 4) {
        float4 a  = *(const float4*)&A1[h];
        float4 w1 = *(const float4*)&outW[h];
        acc += a.x*w1.x + a.y*w1.y + a.z*w1.z + a.w*w1.w;
        float4 a2 = *(const float4*)&A2[h];
        float4 w2 = *(const float4*)&outW[HDIM + h];
        acc += a2.x*w2.x + a2.y*w2.y + a2.z*w2.z + a2.w*w2.w;
    }
#pragma unroll
    for (int off = 16; off; off >>= 1)
        acc += __shfl_down_sync(0xffffffffu, acc, off);
    if (lane == 0) out[w] = 1.f / (1.f + __expf(-(acc + outb[0])));
}

// ---------------------------------------------------------------------------
extern "C" void kernel_launch(void* const* d_in, const int* in_sizes, int n_in,
                              void* d_out, int out_size)
{
    const float* received = (const float*)d_in[0];
    const float* r1_Wih0  = (const float*)d_in[1];
    const float* r1_Whh0  = (const float*)d_in[2];
    const float* r1_bih0  = (const float*)d_in[3];
    const float* r1_bhh0  = (const float*)d_in[4];
    const float* r1_Wih1  = (const float*)d_in[5];
    const float* r1_Whh1  = (const float*)d_in[6];
    const float* r1_bih1  = (const float*)d_in[7];
    const float* r1_bhh1  = (const float*)d_in[8];
    const float* r2_Wih0  = (const float*)d_in[9];
    const float* r2_Whh0  = (const float*)d_in[10];
    const float* r2_bih0  = (const float*)d_in[11];
    const float* r2_bhh0  = (const float*)d_in[12];
    const float* r2_Wih1  = (const float*)d_in[13];
    const float* r2_Whh1  = (const float*)d_in[14];
    const float* r2_bih1  = (const float*)d_in[15];
    const float* r2_bhh1  = (const float*)d_in[16];
    const float* attn_w   = (const float*)d_in[17];
    const float* fc_W     = (const float*)d_in[18];
    const float* fc_b     = (const float*)d_in[19];
    const float* out_W    = (const float*)d_in[20];
    const float* out_b    = (const float*)d_in[21];
    float* out = (float*)d_out;

    float* d_xw1;   cudaGetSymbolAddress((void**)&d_xw1,   g_xw1);
    float* d_h1;    cudaGetSymbolAddress((void**)&d_h1,    g_h1);
    float* d_gout;  cudaGetSymbolAddress((void**)&d_gout,  g_out);
    float* d_cat;   cudaGetSymbolAddress((void**)&d_cat,   g_cat);
    float* d_fused; cudaGetSymbolAddress((void**)&d_fused, g_fused);

    cudaFuncSetAttribute(k_rec_mma<1>, cudaFuncAttributeMaxDynamicSharedMemorySize, REC_SMEM);
    cudaFuncSetAttribute(k_rec_mma<0>, cudaFuncAttributeMaxDynamicSharedMemorySize, REC_SMEM);
    cudaFuncSetAttribute(k_mma,        cudaFuncAttributeMaxDynamicSharedMemorySize, MM_SMEM);

    // 1. convert the four 768x256 recurrent matrices to bf16
    k_prep<<<(4*G3*HDIM + 255)/256, 256>>>(r1_Whh0, r2_Whh0, r1_Whh1, r2_Whh1);
    // 2. layer-0 recurrence (tensor-core) with fused input projection
    k_rec_mma<1><<<dim3(BATCH/TBR, 2), 256, REC_SMEM>>>((const float*)0, received,
                                         r1_Wih0, r2_Wih0, r1_bih0, r2_bih0,
                                         0, r1_bhh0, r2_bhh0, d_h1);
    // 3. xw1 = h1 @ Wih1.T + bih1 — Markidis bf16 mma GEMM
    k_mma<<<dim3(G3/128, BL/128, 2), 256, MM_SMEM>>>(
        d_h1, (size_t)BL*HDIM, r1_Wih1, r2_Wih1, r1_bih1, r2_bih1,
        d_xw1, (size_t)BL*G3, G3, HDIM);
    // 4. layer-1 recurrence (tensor-core)
    k_rec_mma<0><<<dim3(BATCH/TBR, 2), 256, REC_SMEM>>>(d_xw1, (const float*)0,
                                         (const float*)0, (const float*)0,
                                         (const float*)0, (const float*)0,
                                         2, r1_bhh1, r2_bhh1, d_gout);
    // 5. attention scalars q,e
    k_qe<<<dim3(BL/8, 2), 256>>>(attn_w);
    // 6. windowed softmax attention + concat
    k_attn<<<dim3(BM95, 2), 256>>>();
    // 7. FC — Markidis bf16 mma GEMM
    k_mma<<<dim3(HDIM/128, (2*BM95)/128, 1), 256, MM_SMEM>>>(
        d_cat, 0, fc_W, fc_W, fc_b, fc_b,
        d_fused, 0, HDIM, 2*HDIM);
    // 8. final projection + sigmoid
    k_final<<<BL/8, 256>>>(out_W, out_b, out);
}

// round 14
// speedup vs baseline: 1.1825x; 1.1825x over previous
#include <cuda_runtime.h>
#include <math.h>

#define BATCH 512
#define LSEQ  100
#define NINPUT 3
#define HDIM  256
#define G3    768
#define DSH   10
#define WINW  5
#define MSEQ  95          // LSEQ - WINW

#define BL    (BATCH*LSEQ)      // 51200
#define BM95  (BATCH*MSEQ)      // 48640

typedef unsigned long long u64;
typedef unsigned short u16;

// ---------------- scratch (static device memory; no allocations) ----------
__device__ float  g_xw1 [2*BL*G3];          // layer-1 gate inputs, per GRU
__device__ float  g_h1  [2*BL*HDIM];        // layer-0 outputs
__device__ float  g_out [2*BL*HDIM];        // layer-1 outputs (out1/out2)
__device__ float  g_q   [2*BL];
__device__ float  g_e   [2*BL];
__device__ float  g_cat [2*BM95*2*HDIM];    // [c, out_shift] concat for FC
__device__ float  g_fused[2*BM95*HDIM];     // FC output
__device__ u16    g_wB  [4*G3*HDIM];        // Whh bf16, [slot][g=768][k=256]
// slots: 0=r1_Whh0 1=r2_Whh0 2=r1_Whh1 3=r2_Whh1

__device__ __forceinline__ float sigf(float x) { return 1.f / (1.f + __expf(-x)); }

// round-to-nearest-even fp32 -> bf16 bits
__device__ __forceinline__ unsigned bfr(float f) {
    unsigned u = __float_as_uint(f);
    return (u + 0x7FFFu + ((u >> 16) & 1u)) >> 16;
}
__device__ __forceinline__ unsigned pack_bf(float lo, float hi) {
    unsigned r; asm("cvt.rn.bf16x2.f32 %0, %1, %2;" : "=r"(r) : "f"(hi), "f"(lo));
    return r;
}

#define LDMX4(r0,r1,r2,r3,ad) \
    asm volatile("ldmatrix.sync.aligned.m8n8.x4.shared.b16 {%0,%1,%2,%3}, [%4];" \
        : "=r"(r0),"=r"(r1),"=r"(r2),"=r"(r3) : "r"(ad))
#define LDMX2(r0,r1,ad) \
    asm volatile("ldmatrix.sync.aligned.m8n8.x2.shared.b16 {%0,%1}, [%2];" \
        : "=r"(r0),"=r"(r1) : "r"(ad))
#define MMA16816(acc,a,b0v,b1v) \
    asm volatile("mma.sync.aligned.m16n8k16.row.col.f32.bf16.bf16.f32 " \
        "{%0,%1,%2,%3}, {%4,%5,%6,%7}, {%8,%9}, {%0,%1,%2,%3};" \
        : "+f"(acc[0]),"+f"(acc[1]),"+f"(acc[2]),"+f"(acc[3]) \
        : "r"(a[0]),"r"(a[1]),"r"(a[2]),"r"(a[3]),"r"(b0v),"r"(b1v))
#define STCLU64(ad, v) \
    asm volatile("st.shared::cluster.b64 [%0], %1;" :: "r"(ad), "l"(v) : "memory")

// ---------------- weight prep: Whh fp32 -> bf16 (same layout) --------------
__global__ void k_prep(const float* __restrict__ w0, const float* __restrict__ w1,
                       const float* __restrict__ w2, const float* __restrict__ w3)
{
    int idx = blockIdx.x * blockDim.x + threadIdx.x;
    if (idx >= 4 * G3 * HDIM) return;
    int m = idx / (G3 * HDIM);
    int rem = idx % (G3 * HDIM);
    const float* W = (m == 0) ? w0 : (m == 1) ? w1 : (m == 2) ? w2 : w3;
    g_wB[idx] = (u16)bfr(W[rem]);
}

// ---------------- GRU recurrence: 4-CTA cluster, W SMEM-resident ------------
// Cluster handles 32 batch rows of one GRU. Rank owns h-columns
// [64*rank, 64*rank+64) = 192 W rows, resident in SMEM for all 100 steps.
// Per step: gates[32,192] = h[32,256] @ Wownᵀ via mma.sync (h = hi+lo bf16
// Markidis, double-buffered, cluster-shared); pointwise on own 64 columns;
// DSMEM-broadcast new h stripe to all 4 CTAs; ONE cluster barrier per step.
#define RSTR 264        // halves per W/hA row (256 + 8 pad)
#define GST2 200        // floats per gates row (192 + 8 pad)
#define OFF_W    0
#define OFF_AH0  101376
#define OFF_AL0  118272
#define OFF_AH1  135168
#define OFF_AL1  152064
#define OFF_G    168960
#define OFF_WS   194560
#define RECC_SMEM 197632

template<int FUSE>
__global__ void __launch_bounds__(256, 1) __cluster_dims__(4, 1, 1)
k_rec_clu(const float* __restrict__ xw_base, const float* __restrict__ xin,
          const float* __restrict__ Wih_0, const float* __restrict__ Wih_1,
          const float* __restrict__ bih_0, const float* __restrict__ bih_1,
          int wslot,
          const float* __restrict__ bhh_0, const float* __restrict__ bhh_1,
          float* __restrict__ hout_base)
{
    extern __shared__ __align__(16) char dsm[];
    unsigned sb;
    asm("{ .reg .u64 t; cvta.to.shared.u64 t, %1; cvt.u32.u64 %0, t; }"
        : "=r"(sb) : "l"(dsm));

    int r   = blockIdx.y;
    unsigned rank;
    asm("mov.u32 %0, %%cluster_ctarank;" : "=r"(rank));
    int tid = threadIdx.x;
    int wid = tid >> 5, lane = tid & 31;
    int b0  = (blockIdx.x >> 2) * 32;

    const u16*   wbf  = g_wB + (size_t)(wslot + r) * (G3 * HDIM);
    const float* bhh  = r ? bhh_1 : bhh_0;
    const float* xw   = xw_base ? (xw_base + (size_t)r * BL * G3) : (const float*)0;
    float*       hout = hout_base + (size_t)r * BL * HDIM;

    // ---- one-time: stage this rank's 192 W rows (bf16) into SMEM ----
    // local row n = g*64 + c  <->  global W row g*256 + rank*64 + c
    for (int idx = tid; idx < 192 * 64; idx += 256) {
        int n = idx >> 6, kq = idx & 63;                 // kq: 4-half unit
        int grow = (n >> 6) * 256 + (int)rank * 64 + (n & 63);
        u64 v = *(const u64*)(wbf + grow * HDIM + kq * 4);
        *(u64*)(dsm + OFF_W + 2 * n * RSTR + kq * 8) = v;
    }
    // zero both hA double buffers (hi+lo): 67584 bytes
    for (int idx = tid; idx < 16896; idx += 256)
        ((unsigned*)(dsm + OFF_AH0))[idx] = 0;
    // layer-0 input-projection rows for this rank's columns: [192][w0,w1,w2,bih]
    if (FUSE && tid < 192) {
        const float* Wih = r ? Wih_1 : Wih_0;
        const float* bih = r ? bih_1 : bih_0;
        int grow = (tid >> 6) * 256 + (int)rank * 64 + (tid & 63);
        *(float4*)(dsm + OFF_WS + tid * 16) =
            make_float4(Wih[grow*3+0], Wih[grow*3+1], Wih[grow*3+2], bih[grow]);
    }

    // ---- pointwise thread mapping: row pi, 8 columns starting c8 ----
    int pi = tid >> 3;                // batch row 0..31
    int c8 = (tid & 7) * 8;           // local column base 0..56
    int j0 = (int)rank * 64 + c8;     // global h column base

    float4 bhrA = *(const float4*)&bhh[j0];
    float4 bhrB = *(const float4*)&bhh[j0 + 4];
    float4 bhzA = *(const float4*)&bhh[HDIM + j0];
    float4 bhzB = *(const float4*)&bhh[HDIM + j0 + 4];
    float4 bhnA = *(const float4*)&bhh[2*HDIM + j0];
    float4 bhnB = *(const float4*)&bhh[2*HDIM + j0 + 4];
    float bhr[8] = {bhrA.x,bhrA.y,bhrA.z,bhrA.w,bhrB.x,bhrB.y,bhrB.z,bhrB.w};
    float bhz[8] = {bhzA.x,bhzA.y,bhzA.z,bhzA.w,bhzB.x,bhzB.y,bhzB.z,bhzB.w};
    float bhn[8] = {bhnA.x,bhnA.y,bhnA.z,bhnA.w,bhnB.x,bhnB.y,bhnB.z,bhnB.w};

    float hp[8];
#pragma unroll
    for (int q = 0; q < 8; q++) hp[q] = 0.f;

    // DSMEM peer base addresses (mapa once; identical layout in all ranks)
    unsigned peer[4];
#pragma unroll
    for (int d = 0; d < 4; d++)
        asm("mapa.shared::cluster.u32 %0, %1, %2;" : "=r"(peer[d]) : "r"(sb), "r"(d));

    // prefetch step-0 gate inputs
    float xg[24]; float x3[3];
    if (FUSE) {
        const float* xp = xin + ((size_t)(b0 + pi) * LSEQ + 0) * NINPUT;
        x3[0] = xp[0]; x3[1] = xp[1]; x3[2] = xp[2];
    } else {
        const float* xp = xw + ((size_t)(b0 + pi) * LSEQ + 0) * G3;
        *(float4*)&xg[0]  = *(const float4*)&xp[j0];
        *(float4*)&xg[4]  = *(const float4*)&xp[j0 + 4];
        *(float4*)&xg[8]  = *(const float4*)&xp[HDIM + j0];
        *(float4*)&xg[12] = *(const float4*)&xp[HDIM + j0 + 4];
        *(float4*)&xg[16] = *(const float4*)&xp[2*HDIM + j0];
        *(float4*)&xg[20] = *(const float4*)&xp[2*HDIM + j0 + 4];
    }

    __syncthreads();
    asm volatile("barrier.cluster.arrive.aligned;" ::: "memory");

    for (int t = 0; t < LSEQ; t++) {
        asm volatile("barrier.cluster.wait.aligned;" ::: "memory");

        unsigned bAhi = sb + ((t & 1) ? OFF_AH1 : OFF_AH0);
        unsigned bAlo = sb + ((t & 1) ? OFF_AL1 : OFF_AL0);

        float acc[2][3][4];
#pragma unroll
        for (int mt = 0; mt < 2; mt++)
#pragma unroll
            for (int nt = 0; nt < 3; nt++)
#pragma unroll
                for (int q = 0; q < 4; q++) acc[mt][nt][q] = 0.f;

#pragma unroll 4
        for (int ks = 0; ks < 16; ks++) {
            unsigned ahi[2][4], alo[2][4];
#pragma unroll
            for (int mt = 0; mt < 2; mt++) {
                unsigned ao = 2u * ((mt*16 + (lane & 15)) * RSTR
                                    + ks*16 + (lane >> 4) * 8);
                LDMX4(ahi[mt][0], ahi[mt][1], ahi[mt][2], ahi[mt][3], bAhi + ao);
                LDMX4(alo[mt][0], alo[mt][1], alo[mt][2], alo[mt][3], bAlo + ao);
            }
#pragma unroll
            for (int nt = 0; nt < 3; nt++) {
                int n0 = wid * 24 + nt * 8;
                unsigned bo = sb + OFF_W + 2u * ((n0 + (lane & 7)) * RSTR
                                                 + ks*16 + ((lane >> 3) & 1) * 8);
                unsigned bf0, bf1;
                LDMX2(bf0, bf1, bo);
#pragma unroll
                for (int mt = 0; mt < 2; mt++) {
                    MMA16816(acc[mt][nt], ahi[mt], bf0, bf1);
                    MMA16816(acc[mt][nt], alo[mt], bf0, bf1);
                }
            }
        }

        // write gates [32][GST2]
        {
            int gr = lane >> 2, gc = (lane & 3) * 2;
#pragma unroll
            for (int mt = 0; mt < 2; mt++)
#pragma unroll
                for (int nt = 0; nt < 3; nt++) {
                    int n0 = wid * 24 + nt * 8 + gc;
                    unsigned a0 = sb + OFF_G + 4u*((mt*16 + gr) * GST2 + n0);
                    unsigned a1 = sb + OFF_G + 4u*((mt*16 + gr + 8) * GST2 + n0);
                    asm volatile("st.shared.v2.f32 [%0], {%1, %2};"
                                 :: "r"(a0), "f"(acc[mt][nt][0]), "f"(acc[mt][nt][1]) : "memory");
                    asm volatile("st.shared.v2.f32 [%0], {%1, %2};"
                                 :: "r"(a1), "f"(acc[mt][nt][2]), "f"(acc[mt][nt][3]) : "memory");
                }
        }
        __syncthreads();

        // pointwise: row pi, local cols c8..c8+7
        const float* gp = (const float*)(dsm + OFF_G) + pi * GST2;
        float4 r0v = *(const float4*)&gp[c8],       r1v = *(const float4*)&gp[c8 + 4];
        float4 z0v = *(const float4*)&gp[64 + c8],  z1v = *(const float4*)&gp[64 + c8 + 4];
        float4 n0v = *(const float4*)&gp[128 + c8], n1v = *(const float4*)&gp[128 + c8 + 4];
        float sr[8] = {r0v.x,r0v.y,r0v.z,r0v.w,r1v.x,r1v.y,r1v.z,r1v.w};
        float sz[8] = {z0v.x,z0v.y,z0v.z,z0v.w,z1v.x,z1v.y,z1v.z,z1v.w};
        float sn[8] = {n0v.x,n0v.y,n0v.z,n0v.w,n1v.x,n1v.y,n1v.z,n1v.w};

        float hn[8];
#pragma unroll
        for (int q = 0; q < 8; q++) {
            float gxr, gxz, gxn;
            if (FUSE) {
                float4 wr = *(const float4*)(dsm + OFF_WS + (      c8 + q) * 16);
                float4 wz = *(const float4*)(dsm + OFF_WS + ( 64 + c8 + q) * 16);
                float4 wn = *(const float4*)(dsm + OFF_WS + (128 + c8 + q) * 16);
                gxr = wr.w + x3[0]*wr.x + x3[1]*wr.y + x3[2]*wr.z;
                gxz = wz.w + x3[0]*wz.x + x3[1]*wz.y + x3[2]*wz.z;
                gxn = wn.w + x3[0]*wn.x + x3[1]*wn.y + x3[2]*wn.z;
            } else {
                gxr = xg[q]; gxz = xg[8 + q]; gxn = xg[16 + q];
            }
            float rg = sigf(gxr + sr[q] + bhr[q]);
            float zg = sigf(gxz + sz[q] + bhz[q]);
            float ng = tanhf(gxn + rg * (sn[q] + bhn[q]));
            hn[q] = (1.f - zg) * ng + zg * hp[q];
            hp[q] = hn[q];
        }
        // store to gmem
        {
            float* hp_out = &hout[((size_t)(b0 + pi) * LSEQ + t) * HDIM + j0];
            *(float4*)&hp_out[0] = make_float4(hn[0], hn[1], hn[2], hn[3]);
            *(float4*)&hp_out[4] = make_float4(hn[4], hn[5], hn[6], hn[7]);
        }
        // pack hi/lo bf16 and broadcast to all 4 CTAs' hA buf[(t+1)&1]
        {
            unsigned hiw[4], low[4];
#pragma unroll
            for (int p = 0; p < 4; p++) {
                unsigned h0 = bfr(hn[2*p]), h1 = bfr(hn[2*p+1]);
                hiw[p] = h0 | (h1 << 16);
                float b0f = __uint_as_float(h0 << 16);
                float b1f = __uint_as_float(h1 << 16);
                low[p] = pack_bf(hn[2*p] - b0f, hn[2*p+1] - b1f);
            }
            u64 hi01, hi23, lo01, lo23;
            asm("mov.b64 %0, {%1, %2};" : "=l"(hi01) : "r"(hiw[0]), "r"(hiw[1]));
            asm("mov.b64 %0, {%1, %2};" : "=l"(hi23) : "r"(hiw[2]), "r"(hiw[3]));
            asm("mov.b64 %0, {%1, %2};" : "=l"(lo01) : "r"(low[0]), "r"(low[1]));
            asm("mov.b64 %0, {%1, %2};" : "=l"(lo23) : "r"(low[2]), "r"(low[3]));
            unsigned hiOff = (((t+1) & 1) ? OFF_AH1 : OFF_AH0) + 2u*(pi * RSTR + j0);
            unsigned loOff = (((t+1) & 1) ? OFF_AL1 : OFF_AL0) + 2u*(pi * RSTR + j0);
#pragma unroll
            for (int d = 0; d < 4; d++) {
                STCLU64(peer[d] + hiOff,     hi01);
                STCLU64(peer[d] + hiOff + 8, hi23);
                STCLU64(peer[d] + loOff,     lo01);
                STCLU64(peer[d] + loOff + 8, lo23);
            }
        }
        // prefetch next step's gate inputs
        if (t + 1 < LSEQ) {
            if (FUSE) {
                const float* xp = xin + ((size_t)(b0 + pi) * LSEQ + t + 1) * NINPUT;
                x3[0] = xp[0]; x3[1] = xp[1]; x3[2] = xp[2];
            } else {
                const float* xp = xw + ((size_t)(b0 + pi) * LSEQ + t + 1) * G3;
                *(float4*)&xg[0]  = *(const float4*)&xp[j0];
                *(float4*)&xg[4]  = *(const float4*)&xp[j0 + 4];
                *(float4*)&xg[8]  = *(const float4*)&xp[HDIM + j0];
                *(float4*)&xg[12] = *(const float4*)&xp[HDIM + j0 + 4];
                *(float4*)&xg[16] = *(const float4*)&xp[2*HDIM + j0];
                *(float4*)&xg[20] = *(const float4*)&xp[2*HDIM + j0 + 4];
            }
        }
        asm volatile("barrier.cluster.arrive.aligned;" ::: "memory");
    }
    asm volatile("barrier.cluster.wait.aligned;" ::: "memory");
}

// ==================== Markidis bf16 GEMM (3-mma, ~fp32 accuracy) ============
#define LDSTR 72
#define MM_SMEM (4 * 128 * LDSTR * 2)   // Ahi, Alo, Bhi, Blo

__global__ void __launch_bounds__(256, 2)
k_mma(const float* __restrict__ A, size_t strideAz,
      const float* __restrict__ B0, const float* __restrict__ B1,
      const float* __restrict__ bias0, const float* __restrict__ bias1,
      float* __restrict__ C, size_t strideCz, int Ntot, int K)
{
    extern __shared__ __align__(16) char smm[];
    unsigned sb;
    asm("{ .reg .u64 t; cvta.to.shared.u64 t, %1; cvt.u32.u64 %0, t; }"
        : "=r"(sb) : "l"(smm));
    unsigned sAhi = sb;
    unsigned sAlo = sb + 128*LDSTR*2;
    unsigned sBhi = sb + 2*128*LDSTR*2;
    unsigned sBlo = sb + 3*128*LDSTR*2;

    int z = blockIdx.z;
    const float* Az   = A + (size_t)z * strideAz;
    const float* Bw   = z ? B1 : B0;
    const float* bias = z ? bias1 : bias0;
    float*       Cz   = C + (size_t)z * strideCz;

    int tid = threadIdx.x;
    int wid = tid >> 5, lane = tid & 31;
    int wm = wid & 3, wn = wid >> 2;
    int bm = blockIdx.y * 128, bn = blockIdx.x * 128;

    float acc[2][8][4];
#pragma unroll
    for (int mt = 0; mt < 2; mt++)
#pragma unroll
        for (int nt = 0; nt < 8; nt++)
#pragma unroll
            for (int q = 0; q < 4; q++) acc[mt][nt][q] = 0.f;

    int lrow = tid >> 1, lh = tid & 1;

    for (int kc = 0; kc < K; kc += 64) {
        __syncthreads();
#pragma unroll
        for (int s = 0; s < 2; s++) {
            const float* src = s ? Bw : Az;
            int gr = s ? bn : bm;
            unsigned dhi = s ? sBhi : sAhi;
            unsigned dlo = s ? sBlo : sAlo;
#pragma unroll
            for (int i = 0; i < 8; i++) {
                float4 v = *(const float4*)&src[(size_t)(gr + lrow) * K + kc + lh*32 + i*4];
                unsigned hi0 = pack_bf(v.x, v.y), hi1 = pack_bf(v.z, v.w);
                float bxx = __uint_as_float((hi0 & 0xFFFFu) << 16);
                float bxy = __uint_as_float(hi0 & 0xFFFF0000u);
                float bxz = __uint_as_float((hi1 & 0xFFFFu) << 16);
                float bxw = __uint_as_float(hi1 & 0xFFFF0000u);
                unsigned lo0 = pack_bf(v.x - bxx, v.y - bxy);
                unsigned lo1 = pack_bf(v.z - bxz, v.w - bxw);
                unsigned off = 2u*(lrow*LDSTR + lh*32 + i*4);
                u64 ph, pl;
                asm("mov.b64 %0, {%1, %2};" : "=l"(ph) : "r"(hi0), "r"(hi1));
                asm("mov.b64 %0, {%1, %2};" : "=l"(pl) : "r"(lo0), "r"(lo1));
                asm volatile("st.shared.b64 [%0], %1;" :: "r"(dhi + off), "l"(ph) : "memory");
                asm volatile("st.shared.b64 [%0], %1;" :: "r"(dlo + off), "l"(pl) : "memory");
            }
        }
        __syncthreads();

#pragma unroll
        for (int ks = 0; ks < 4; ks++) {
            unsigned ahi[2][4], alo[2][4];
#pragma unroll
            for (int mt = 0; mt < 2; mt++) {
                unsigned colo = 2u*((wm*32 + mt*16 + (lane & 15))*LDSTR
                                    + ks*16 + (lane>>4)*8);
                LDMX4(ahi[mt][0], ahi[mt][1], ahi[mt][2], ahi[mt][3], sAhi + colo);
                LDMX4(alo[mt][0], alo[mt][1], alo[mt][2], alo[mt][3], sAlo + colo);
            }
#pragma unroll
            for (int nt = 0; nt < 8; nt++) {
                unsigned boff = 2u*((wn*64 + nt*8 + (lane & 7))*LDSTR
                                    + ks*16 + ((lane>>3)&1)*8);
                unsigned bh0, bh1, bl0, bl1;
                LDMX2(bh0, bh1, sBhi + boff);
                LDMX2(bl0, bl1, sBlo + boff);
#pragma unroll
                for (int mt = 0; mt < 2; mt++) {
                    MMA16816(acc[mt][nt], ahi[mt], bh0, bh1);
                    MMA16816(acc[mt][nt], ahi[mt], bl0, bl1);
                    MMA16816(acc[mt][nt], alo[mt], bh0, bh1);
                }
            }
        }
    }

    int row0 = bm + wm*32;
    int col0 = bn + wn*64;
#pragma unroll
    for (int mt = 0; mt < 2; mt++) {
        int r0 = row0 + mt*16 + (lane >> 2);
#pragma unroll
        for (int nt = 0; nt < 8; nt++) {
            int c = col0 + nt*8 + (lane & 3) * 2;
            float b0v = bias[c], b1v = bias[c + 1];
            float2 v0 = make_float2(acc[mt][nt][0] + b0v, acc[mt][nt][1] + b1v);
            float2 v1 = make_float2(acc[mt][nt][2] + b0v, acc[mt][nt][3] + b1v);
            *(float2*)&Cz[(size_t)r0 * Ntot + c]       = v0;
            *(float2*)&Cz[(size_t)(r0 + 8) * Ntot + c] = v1;
        }
    }
}

// ---------------- q = out@aw[:H], e = out@aw[H:] (warp per (b,l)) ----------
__global__ void k_qe(const float* __restrict__ attn_w)
{
    int r    = blockIdx.y;
    int w    = blockIdx.x * 8 + (threadIdx.x >> 5);
    int lane = threadIdx.x & 31;
    const float* o = g_out + ((size_t)r * BL + w) * HDIM;
    float q = 0.f, e = 0.f;
#pragma unroll
    for (int h = lane * 8; h < lane * 8 + 8; h += 4) {
        float4 ov = *(const float4*)&o[h];
        float4 a1 = *(const float4*)&attn_w[h];
        float4 a2 = *(const float4*)&attn_w[HDIM + h];
        q += ov.x*a1.x + ov.y*a1.y + ov.z*a1.z + ov.w*a1.w;
        e += ov.x*a2.x + ov.y*a2.y + ov.z*a2.z + ov.w*a2.w;
    }
#pragma unroll
    for (int off = 16; off; off >>= 1) {
        q += __shfl_down_sync(0xffffffffu, q, off);
        e += __shfl_down_sync(0xffffffffu, e, off);
    }
    if (lane == 0) { g_q[r * BL + w] = q; g_e[r * BL + w] = e; }
}

// ---------------- windowed attention + concat for FC ----------------------
__global__ void k_attn()
{
    int r    = blockIdx.y;
    int bl95 = blockIdx.x;
    int b    = bl95 / MSEQ, l = bl95 % MSEQ;
    int h    = threadIdx.x;

    const float* qrow = g_q + r * BL + b * LSEQ;
    const float* erow = g_e + r * BL + b * LSEQ;
    float qv = qrow[l + WINW];
    float s[WINW];
    float mx = -1e30f;
#pragma unroll
    for (int k = 0; k < WINW; k++) { s[k] = qv + erow[l + k]; mx = fmaxf(mx, s[k]); }
    float sum = 0.f;
#pragma unroll
    for (int k = 0; k < WINW; k++) { s[k] = __expf(s[k] - mx); sum += s[k]; }
    float inv = 1.f / sum;

    const float* o = g_out + ((size_t)r * BL + b * LSEQ + l) * HDIM;
    float c = 0.f;
#pragma unroll
    for (int k = 0; k < WINW; k++) c += s[k] * inv * o[k * HDIM + h];

    size_t m = (size_t)r * BM95 + bl95;
    g_cat[m * (2*HDIM) + h]        = c;
    g_cat[m * (2*HDIM) + HDIM + h] = o[WINW * HDIM + h];
}

// ---------------- final head: concat(rnn1[b,l], rnn2[b,min(l+D,99)]) ------
__global__ void k_final(const float* __restrict__ outW, const float* __restrict__ outb,
                        float* __restrict__ out)
{
    int w    = blockIdx.x * 8 + (threadIdx.x >> 5);
    int lane = threadIdx.x & 31;
    int b = w / LSEQ, l = w % LSEQ;

    const float* A1 = (l < WINW)
        ? (g_out   + ((size_t)(b * LSEQ + l)) * HDIM)
        : (g_fused + ((size_t)(b * MSEQ + l - WINW)) * HDIM);
    int lidx = min(l + DSH, LSEQ - 1);
    const float* A2 = (lidx < WINW)
        ? (g_out   + ((size_t)BL + b * LSEQ + lidx) * HDIM)
        : (g_fused + ((size_t)BM95 + b * MSEQ + lidx - WINW) * HDIM);

    float acc = 0.f;
#pragma unroll
    for (int h = lane * 8; h < lane * 8 + 8; h += 4) {
        float4 a  = *(const float4*)&A1[h];
        float4 w1 = *(const float4*)&outW[h];
        acc += a.x*w1.x + a.y*w1.y + a.z*w1.z + a.w*w1.w;
        float4 a2 = *(const float4*)&A2[h];
        float4 w2 = *(const float4*)&outW[HDIM + h];
        acc += a2.x*w2.x + a2.y*w2.y + a2.z*w2.z + a2.w*w2.w;
    }
#pragma unroll
    for (int off = 16; off; off >>= 1)
        acc += __shfl_down_sync(0xffffffffu, acc, off);
    if (lane == 0) out[w] = 1.f / (1.f + __expf(-(acc + outb[0])));
}

// ---------------------------------------------------------------------------
extern "C" void kernel_launch(void* const* d_in, const int* in_sizes, int n_in,
                              void* d_out, int out_size)
{
    const float* received = (const float*)d_in[0];
    const float* r1_Wih0  = (const float*)d_in[1];
    const float* r1_Whh0  = (const float*)d_in[2];
    const float* r1_bih0  = (const float*)d_in[3];
    const float* r1_bhh0  = (const float*)d_in[4];
    const float* r1_Wih1  = (const float*)d_in[5];
    const float* r1_Whh1  = (const float*)d_in[6];
    const float* r1_bih1  = (const float*)d_in[7];
    const float* r1_bhh1  = (const float*)d_in[8];
    const float* r2_Wih0  = (const float*)d_in[9];
    const float* r2_Whh0  = (const float*)d_in[10];
    const float* r2_bih0  = (const float*)d_in[11];
    const float* r2_bhh0  = (const float*)d_in[12];
    const float* r2_Wih1  = (const float*)d_in[13];
    const float* r2_Whh1  = (const float*)d_in[14];
    const float* r2_bih1  = (const float*)d_in[15];
    const float* r2_bhh1  = (const float*)d_in[16];
    const float* attn_w   = (const float*)d_in[17];
    const float* fc_W     = (const float*)d_in[18];
    const float* fc_b     = (const float*)d_in[19];
    const float* out_W    = (const float*)d_in[20];
    const float* out_b    = (const float*)d_in[21];
    float* out = (float*)d_out;

    float* d_xw1;   cudaGetSymbolAddress((void**)&d_xw1,   g_xw1);
    float* d_h1;    cudaGetSymbolAddress((void**)&d_h1,    g_h1);
    float* d_gout;  cudaGetSymbolAddress((void**)&d_gout,  g_out);
    float* d_cat;   cudaGetSymbolAddress((void**)&d_cat,   g_cat);
    float* d_fused; cudaGetSymbolAddress((void**)&d_fused, g_fused);

    cudaFuncSetAttribute(k_rec_clu<1>, cudaFuncAttributeMaxDynamicSharedMemorySize, RECC_SMEM);
    cudaFuncSetAttribute(k_rec_clu<0>, cudaFuncAttributeMaxDynamicSharedMemorySize, RECC_SMEM);
    cudaFuncSetAttribute(k_mma,        cudaFuncAttributeMaxDynamicSharedMemorySize, MM_SMEM);

    // 1. convert the four 768x256 recurrent matrices to bf16
    k_prep<<<(4*G3*HDIM + 255)/256, 256>>>(r1_Whh0, r2_Whh0, r1_Whh1, r2_Whh1);
    // 2. layer-0 recurrence (cluster, resident W) with fused input projection
    k_rec_clu<1><<<dim3(64, 2), 256, RECC_SMEM>>>((const float*)0, received,
                                         r1_Wih0, r2_Wih0, r1_bih0, r2_bih0,
                                         0, r1_bhh0, r2_bhh0, d_h1);
    // 3. xw1 = h1 @ Wih1.T + bih1 — Markidis bf16 mma GEMM
    k_mma<<<dim3(G3/128, BL/128, 2), 256, MM_SMEM>>>(
        d_h1, (size_t)BL*HDIM, r1_Wih1, r2_Wih1, r1_bih1, r2_bih1,
        d_xw1, (size_t)BL*G3, G3, HDIM);
    // 4. layer-1 recurrence (cluster, resident W)
    k_rec_clu<0><<<dim3(64, 2), 256, RECC_SMEM>>>(d_xw1, (const float*)0,
                                         (const float*)0, (const float*)0,
                                         (const float*)0, (const float*)0,
                                         2, r1_bhh1, r2_bhh1, d_gout);
    // 5. attention scalars q,e
    k_qe<<<dim3(BL/8, 2), 256>>>(attn_w);
    // 6. windowed softmax attention + concat
    k_attn<<<dim3(BM95, 2), 256>>>();
    // 7. FC — Markidis bf16 mma GEMM
    k_mma<<<dim3(HDIM/128, (2*BM95)/128, 1), 256, MM_SMEM>>>(
        d_cat, 0, fc_W, fc_W, fc_b, fc_b,
        d_fused, 0, HDIM, 2*HDIM);
    // 8. final projection + sigmoid
    k_final<<<BL/8, 256>>>(out_W, out_b, out);
}

// round 15
// speedup vs baseline: 1.6605x; 1.4042x over previous
#include <cuda_runtime.h>
#include <math.h>

#define BATCH 512
#define LSEQ  100
#define NINPUT 3
#define HDIM  256
#define G3    768
#define DSH   10
#define WINW  5
#define MSEQ  95          // LSEQ - WINW

#define BL    (BATCH*LSEQ)      // 51200
#define BM95  (BATCH*MSEQ)      // 48640

typedef unsigned long long u64;
typedef unsigned short u16;

// ---------------- scratch (static device memory; no allocations) ----------
__device__ float  g_xw1 [2*BL*G3];          // layer-1 gate inputs, per GRU
__device__ float  g_h1  [2*BL*HDIM];        // layer-0 outputs
__device__ float  g_out [2*BL*HDIM];        // layer-1 outputs (out1/out2)
__device__ float  g_q   [2*BL];
__device__ float  g_e   [2*BL];
__device__ float  g_cat [2*BM95*2*HDIM];    // [c, out_shift] concat for FC
__device__ float  g_fused[2*BM95*HDIM];     // FC output
__device__ u16    g_wB  [4*G3*HDIM];        // Whh bf16, [slot][g=768][k=256]
// slots: 0=r1_Whh0 1=r2_Whh0 2=r1_Whh1 3=r2_Whh1

// fast sigmoid / tanh (EX2 + RCP MUFU path; err ~1e-6, far under bf16-W error)
__device__ __forceinline__ float sigf(float x) {
    return __fdividef(1.f, 1.f + __expf(-x));
}
__device__ __forceinline__ float tanhfast(float x) {
    return 2.f * __fdividef(1.f, 1.f + __expf(-2.f * x)) - 1.f;
}

// round-to-nearest-even fp32 -> bf16 bits
__device__ __forceinline__ unsigned bfr(float f) {
    unsigned u = __float_as_uint(f);
    return (u + 0x7FFFu + ((u >> 16) & 1u)) >> 16;
}
__device__ __forceinline__ unsigned pack_bf(float lo, float hi) {
    unsigned r; asm("cvt.rn.bf16x2.f32 %0, %1, %2;" : "=r"(r) : "f"(hi), "f"(lo));
    return r;
}

#define LDMX4(r0,r1,r2,r3,ad) \
    asm volatile("ldmatrix.sync.aligned.m8n8.x4.shared.b16 {%0,%1,%2,%3}, [%4];" \
        : "=r"(r0),"=r"(r1),"=r"(r2),"=r"(r3) : "r"(ad))
#define LDMX2(r0,r1,ad) \
    asm volatile("ldmatrix.sync.aligned.m8n8.x2.shared.b16 {%0,%1}, [%2];" \
        : "=r"(r0),"=r"(r1) : "r"(ad))
#define MMA16816(acc,a,b0v,b1v) \
    asm volatile("mma.sync.aligned.m16n8k16.row.col.f32.bf16.bf16.f32 " \
        "{%0,%1,%2,%3}, {%4,%5,%6,%7}, {%8,%9}, {%0,%1,%2,%3};" \
        : "+f"(acc[0]),"+f"(acc[1]),"+f"(acc[2]),"+f"(acc[3]) \
        : "r"(a[0]),"r"(a[1]),"r"(a[2]),"r"(a[3]),"r"(b0v),"r"(b1v))
#define STCLU64(ad, v) \
    asm volatile("st.shared::cluster.b64 [%0], %1;" :: "r"(ad), "l"(v) : "memory")

// ---------------- weight prep: Whh fp32 -> bf16 (same layout) --------------
__global__ void k_prep(const float* __restrict__ w0, const float* __restrict__ w1,
                       const float* __restrict__ w2, const float* __restrict__ w3)
{
    int idx = blockIdx.x * blockDim.x + threadIdx.x;
    if (idx >= 4 * G3 * HDIM) return;
    int m = idx / (G3 * HDIM);
    int rem = idx % (G3 * HDIM);
    const float* W = (m == 0) ? w0 : (m == 1) ? w1 : (m == 2) ? w2 : w3;
    g_wB[idx] = (u16)bfr(W[rem]);
}

// ---------------- GRU recurrence: 4-CTA cluster, W SMEM-resident ------------
// 512 threads (16 warps), cluster of 4 CTAs handles 32 batch rows of one GRU.
// Rank owns h-columns [64*rank, 64*rank+64) = 192 W rows, SMEM-resident.
// Per step: gates[32,192] = h[32,256] @ Wownᵀ via mma.sync (h = hi+lo bf16
// Markidis, double-buffered, cluster-shared); warp grid 2mt x 8wn; pointwise
// 4 cols/thread; DSMEM-broadcast h stripe; ONE cluster barrier per step.
#define RSTR 264        // halves per W/hA row (256 + 8 pad)
#define GST2 200        // floats per gates row (192 + 8 pad)
#define OFF_W    0
#define OFF_AH0  101376
#define OFF_AL0  118272
#define OFF_AH1  135168
#define OFF_AL1  152064
#define OFF_G    168960
#define OFF_WS   194560
#define RECC_SMEM 197632

template<int FUSE>
__global__ void __launch_bounds__(512, 1) __cluster_dims__(4, 1, 1)
k_rec_clu(const float* __restrict__ xw_base, const float* __restrict__ xin,
          const float* __restrict__ Wih_0, const float* __restrict__ Wih_1,
          const float* __restrict__ bih_0, const float* __restrict__ bih_1,
          int wslot,
          const float* __restrict__ bhh_0, const float* __restrict__ bhh_1,
          float* __restrict__ hout_base)
{
    extern __shared__ __align__(16) char dsm[];
    unsigned sb;
    asm("{ .reg .u64 t; cvta.to.shared.u64 t, %1; cvt.u32.u64 %0, t; }"
        : "=r"(sb) : "l"(dsm));

    int r   = blockIdx.y;
    unsigned rank;
    asm("mov.u32 %0, %%cluster_ctarank;" : "=r"(rank));
    int tid = threadIdx.x;
    int wid = tid >> 5, lane = tid & 31;
    int wmt = wid >> 3;               // M half (0/1) this warp computes
    int wn  = wid & 7;                // N slice (24 columns)
    int b0  = (blockIdx.x >> 2) * 32;

    const u16*   wbf  = g_wB + (size_t)(wslot + r) * (G3 * HDIM);
    const float* bhh  = r ? bhh_1 : bhh_0;
    const float* xw   = xw_base ? (xw_base + (size_t)r * BL * G3) : (const float*)0;
    float*       hout = hout_base + (size_t)r * BL * HDIM;

    // ---- one-time: stage this rank's 192 W rows (bf16) into SMEM ----
    for (int idx = tid; idx < 192 * 64; idx += 512) {
        int n = idx >> 6, kq = idx & 63;                 // kq: 4-half unit
        int grow = (n >> 6) * 256 + (int)rank * 64 + (n & 63);
        u64 v = *(const u64*)(wbf + grow * HDIM + kq * 4);
        *(u64*)(dsm + OFF_W + 2 * n * RSTR + kq * 8) = v;
    }
    // zero both hA double buffers (hi+lo)
    for (int idx = tid; idx < 16896; idx += 512)
        ((unsigned*)(dsm + OFF_AH0))[idx] = 0;
    // layer-0 input-projection rows for this rank's columns: [192][w0,w1,w2,bih]
    if (FUSE && tid < 192) {
        const float* Wih = r ? Wih_1 : Wih_0;
        const float* bih = r ? bih_1 : bih_0;
        int grow = (tid >> 6) * 256 + (int)rank * 64 + (tid & 63);
        *(float4*)(dsm + OFF_WS + tid * 16) =
            make_float4(Wih[grow*3+0], Wih[grow*3+1], Wih[grow*3+2], bih[grow]);
    }

    // ---- pointwise thread mapping: row pi, 4 columns starting c4 ----
    int pi = tid >> 4;                // batch row 0..31
    int c4 = (tid & 15) * 4;          // local column base 0..60
    int j0 = (int)rank * 64 + c4;     // global h column base

    float4 bhrv = *(const float4*)&bhh[j0];
    float4 bhzv = *(const float4*)&bhh[HDIM + j0];
    float4 bhnv = *(const float4*)&bhh[2*HDIM + j0];
    float bhr[4] = {bhrv.x, bhrv.y, bhrv.z, bhrv.w};
    float bhz[4] = {bhzv.x, bhzv.y, bhzv.z, bhzv.w};
    float bhn[4] = {bhnv.x, bhnv.y, bhnv.z, bhnv.w};

    float hp[4];
#pragma unroll
    for (int q = 0; q < 4; q++) hp[q] = 0.f;

    // DSMEM peer base addresses
    unsigned peer[4];
#pragma unroll
    for (int d = 0; d < 4; d++)
        asm("mapa.shared::cluster.u32 %0, %1, %2;" : "=r"(peer[d]) : "r"(sb), "r"(d));

    // prefetch step-0 gate inputs
    float xg[12]; float x3[3];
    if (FUSE) {
        const float* xp = xin + ((size_t)(b0 + pi) * LSEQ + 0) * NINPUT;
        x3[0] = xp[0]; x3[1] = xp[1]; x3[2] = xp[2];
    } else {
        const float* xp = xw + ((size_t)(b0 + pi) * LSEQ + 0) * G3;
        *(float4*)&xg[0] = *(const float4*)&xp[j0];
        *(float4*)&xg[4] = *(const float4*)&xp[HDIM + j0];
        *(float4*)&xg[8] = *(const float4*)&xp[2*HDIM + j0];
    }

    __syncthreads();
    asm volatile("barrier.cluster.arrive.aligned;" ::: "memory");

    for (int t = 0; t < LSEQ; t++) {
        asm volatile("barrier.cluster.wait.aligned;" ::: "memory");

        unsigned bAhi = sb + ((t & 1) ? OFF_AH1 : OFF_AH0);
        unsigned bAlo = sb + ((t & 1) ? OFF_AL1 : OFF_AL0);

        float acc[3][4];
#pragma unroll
        for (int nt = 0; nt < 3; nt++)
#pragma unroll
            for (int q = 0; q < 4; q++) acc[nt][q] = 0.f;

#pragma unroll 4
        for (int ks = 0; ks < 16; ks++) {
            unsigned ahi[4], alo[4];
            unsigned ao = 2u * ((wmt*16 + (lane & 15)) * RSTR
                                + ks*16 + (lane >> 4) * 8);
            LDMX4(ahi[0], ahi[1], ahi[2], ahi[3], bAhi + ao);
            LDMX4(alo[0], alo[1], alo[2], alo[3], bAlo + ao);
#pragma unroll
            for (int nt = 0; nt < 3; nt++) {
                int n0 = wn * 24 + nt * 8;
                unsigned bo = sb + OFF_W + 2u * ((n0 + (lane & 7)) * RSTR
                                                 + ks*16 + ((lane >> 3) & 1) * 8);
                unsigned bf0, bf1;
                LDMX2(bf0, bf1, bo);
                MMA16816(acc[nt], ahi, bf0, bf1);
                MMA16816(acc[nt], alo, bf0, bf1);
            }
        }

        // write gates [32][GST2]
        {
            int gr = lane >> 2, gc = (lane & 3) * 2;
#pragma unroll
            for (int nt = 0; nt < 3; nt++) {
                int n0 = wn * 24 + nt * 8 + gc;
                unsigned a0 = sb + OFF_G + 4u*((wmt*16 + gr) * GST2 + n0);
                unsigned a1 = sb + OFF_G + 4u*((wmt*16 + gr + 8) * GST2 + n0);
                asm volatile("st.shared.v2.f32 [%0], {%1, %2};"
                             :: "r"(a0), "f"(acc[nt][0]), "f"(acc[nt][1]) : "memory");
                asm volatile("st.shared.v2.f32 [%0], {%1, %2};"
                             :: "r"(a1), "f"(acc[nt][2]), "f"(acc[nt][3]) : "memory");
            }
        }
        __syncthreads();

        // pointwise: row pi, local cols c4..c4+3
        const float* gp = (const float*)(dsm + OFF_G) + pi * GST2;
        float4 rv = *(const float4*)&gp[c4];
        float4 zv = *(const float4*)&gp[64 + c4];
        float4 nv = *(const float4*)&gp[128 + c4];
        float sr[4] = {rv.x, rv.y, rv.z, rv.w};
        float sz[4] = {zv.x, zv.y, zv.z, zv.w};
        float sn[4] = {nv.x, nv.y, nv.z, nv.w};

        float hn[4];
#pragma unroll
        for (int q = 0; q < 4; q++) {
            float gxr, gxz, gxn;
            if (FUSE) {
                float4 wr = *(const float4*)(dsm + OFF_WS + (      c4 + q) * 16);
                float4 wz = *(const float4*)(dsm + OFF_WS + ( 64 + c4 + q) * 16);
                float4 wn2 = *(const float4*)(dsm + OFF_WS + (128 + c4 + q) * 16);
                gxr = wr.w + x3[0]*wr.x + x3[1]*wr.y + x3[2]*wr.z;
                gxz = wz.w + x3[0]*wz.x + x3[1]*wz.y + x3[2]*wz.z;
                gxn = wn2.w + x3[0]*wn2.x + x3[1]*wn2.y + x3[2]*wn2.z;
            } else {
                gxr = xg[q]; gxz = xg[4 + q]; gxn = xg[8 + q];
            }
            float rg = sigf(gxr + sr[q] + bhr[q]);
            float zg = sigf(gxz + sz[q] + bhz[q]);
            float ng = tanhfast(gxn + rg * (sn[q] + bhn[q]));
            hn[q] = (1.f - zg) * ng + zg * hp[q];
            hp[q] = hn[q];
        }
        // store to gmem
        *(float4*)&hout[((size_t)(b0 + pi) * LSEQ + t) * HDIM + j0] =
            make_float4(hn[0], hn[1], hn[2], hn[3]);

        // pack hi/lo bf16 and broadcast to all 4 CTAs' hA buf[(t+1)&1]
        {
            unsigned hiw[2], low[2];
#pragma unroll
            for (int p = 0; p < 2; p++) {
                unsigned h0 = bfr(hn[2*p]), h1 = bfr(hn[2*p+1]);
                hiw[p] = h0 | (h1 << 16);
                float b0f = __uint_as_float(h0 << 16);
                float b1f = __uint_as_float(h1 << 16);
                low[p] = pack_bf(hn[2*p] - b0f, hn[2*p+1] - b1f);
            }
            u64 hi01, lo01;
            asm("mov.b64 %0, {%1, %2};" : "=l"(hi01) : "r"(hiw[0]), "r"(hiw[1]));
            asm("mov.b64 %0, {%1, %2};" : "=l"(lo01) : "r"(low[0]), "r"(low[1]));
            unsigned hiOff = (((t+1) & 1) ? OFF_AH1 : OFF_AH0) + 2u*(pi * RSTR + j0);
            unsigned loOff = (((t+1) & 1) ? OFF_AL1 : OFF_AL0) + 2u*(pi * RSTR + j0);
#pragma unroll
            for (int d = 0; d < 4; d++) {
                STCLU64(peer[d] + hiOff, hi01);
                STCLU64(peer[d] + loOff, lo01);
            }
        }
        // prefetch next step's gate inputs
        if (t + 1 < LSEQ) {
            if (FUSE) {
                const float* xp = xin + ((size_t)(b0 + pi) * LSEQ + t + 1) * NINPUT;
                x3[0] = xp[0]; x3[1] = xp[1]; x3[2] = xp[2];
            } else {
                const float* xp = xw + ((size_t)(b0 + pi) * LSEQ + t + 1) * G3;
                *(float4*)&xg[0] = *(const float4*)&xp[j0];
                *(float4*)&xg[4] = *(const float4*)&xp[HDIM + j0];
                *(float4*)&xg[8] = *(const float4*)&xp[2*HDIM + j0];
            }
        }
        asm volatile("barrier.cluster.arrive.aligned;" ::: "memory");
    }
    asm volatile("barrier.cluster.wait.aligned;" ::: "memory");
}

// ==================== Markidis bf16 GEMM (3-mma, ~fp32 accuracy) ============
#define LDSTR 72
#define MM_SMEM (4 * 128 * LDSTR * 2)   // Ahi, Alo, Bhi, Blo

__global__ void __launch_bounds__(256, 2)
k_mma(const float* __restrict__ A, size_t strideAz,
      const float* __restrict__ B0, const float* __restrict__ B1,
      const float* __restrict__ bias0, const float* __restrict__ bias1,
      float* __restrict__ C, size_t strideCz, int Ntot, int K)
{
    extern __shared__ __align__(16) char smm[];
    unsigned sb;
    asm("{ .reg .u64 t; cvta.to.shared.u64 t, %1; cvt.u32.u64 %0, t; }"
        : "=r"(sb) : "l"(smm));
    unsigned sAhi = sb;
    unsigned sAlo = sb + 128*LDSTR*2;
    unsigned sBhi = sb + 2*128*LDSTR*2;
    unsigned sBlo = sb + 3*128*LDSTR*2;

    int z = blockIdx.z;
    const float* Az   = A + (size_t)z * strideAz;
    const float* Bw   = z ? B1 : B0;
    const float* bias = z ? bias1 : bias0;
    float*       Cz   = C + (size_t)z * strideCz;

    int tid = threadIdx.x;
    int wid = tid >> 5, lane = tid & 31;
    int wm = wid & 3, wn = wid >> 2;
    int bm = blockIdx.y * 128, bn = blockIdx.x * 128;

    float acc[2][8][4];
#pragma unroll
    for (int mt = 0; mt < 2; mt++)
#pragma unroll
        for (int nt = 0; nt < 8; nt++)
#pragma unroll
            for (int q = 0; q < 4; q++) acc[mt][nt][q] = 0.f;

    int lrow = tid >> 1, lh = tid & 1;

    for (int kc = 0; kc < K; kc += 64) {
        __syncthreads();
#pragma unroll
        for (int s = 0; s < 2; s++) {
            const float* src = s ? Bw : Az;
            int gr = s ? bn : bm;
            unsigned dhi = s ? sBhi : sAhi;
            unsigned dlo = s ? sBlo : sAlo;
#pragma unroll
            for (int i = 0; i < 8; i++) {
                float4 v = *(const float4*)&src[(size_t)(gr + lrow) * K + kc + lh*32 + i*4];
                unsigned hi0 = pack_bf(v.x, v.y), hi1 = pack_bf(v.z, v.w);
                float bxx = __uint_as_float((hi0 & 0xFFFFu) << 16);
                float bxy = __uint_as_float(hi0 & 0xFFFF0000u);
                float bxz = __uint_as_float((hi1 & 0xFFFFu) << 16);
                float bxw = __uint_as_float(hi1 & 0xFFFF0000u);
                unsigned lo0 = pack_bf(v.x - bxx, v.y - bxy);
                unsigned lo1 = pack_bf(v.z - bxz, v.w - bxw);
                unsigned off = 2u*(lrow*LDSTR + lh*32 + i*4);
                u64 ph, pl;
                asm("mov.b64 %0, {%1, %2};" : "=l"(ph) : "r"(hi0), "r"(hi1));
                asm("mov.b64 %0, {%1, %2};" : "=l"(pl) : "r"(lo0), "r"(lo1));
                asm volatile("st.shared.b64 [%0], %1;" :: "r"(dhi + off), "l"(ph) : "memory");
                asm volatile("st.shared.b64 [%0], %1;" :: "r"(dlo + off), "l"(pl) : "memory");
            }
        }
        __syncthreads();

#pragma unroll
        for (int ks = 0; ks < 4; ks++) {
            unsigned ahi[2][4], alo[2][4];
#pragma unroll
            for (int mt = 0; mt < 2; mt++) {
                unsigned colo = 2u*((wm*32 + mt*16 + (lane & 15))*LDSTR
                                    + ks*16 + (lane>>4)*8);
                LDMX4(ahi[mt][0], ahi[mt][1], ahi[mt][2], ahi[mt][3], sAhi + colo);
                LDMX4(alo[mt][0], alo[mt][1], alo[mt][2], alo[mt][3], sAlo + colo);
            }
#pragma unroll
            for (int nt = 0; nt < 8; nt++) {
                unsigned boff = 2u*((wn*64 + nt*8 + (lane & 7))*LDSTR
                                    + ks*16 + ((lane>>3)&1)*8);
                unsigned bh0, bh1, bl0, bl1;
                LDMX2(bh0, bh1, sBhi + boff);
                LDMX2(bl0, bl1, sBlo + boff);
#pragma unroll
                for (int mt = 0; mt < 2; mt++) {
                    MMA16816(acc[mt][nt], ahi[mt], bh0, bh1);
                    MMA16816(acc[mt][nt], ahi[mt], bl0, bl1);
                    MMA16816(acc[mt][nt], alo[mt], bh0, bh1);
                }
            }
        }
    }

    int row0 = bm + wm*32;
    int col0 = bn + wn*64;
#pragma unroll
    for (int mt = 0; mt < 2; mt++) {
        int r0 = row0 + mt*16 + (lane >> 2);
#pragma unroll
        for (int nt = 0; nt < 8; nt++) {
            int c = col0 + nt*8 + (lane & 3) * 2;
            float b0v = bias[c], b1v = bias[c + 1];
            float2 v0 = make_float2(acc[mt][nt][0] + b0v, acc[mt][nt][1] + b1v);
            float2 v1 = make_float2(acc[mt][nt][2] + b0v, acc[mt][nt][3] + b1v);
            *(float2*)&Cz[(size_t)r0 * Ntot + c]       = v0;
            *(float2*)&Cz[(size_t)(r0 + 8) * Ntot + c] = v1;
        }
    }
}

// ---------------- q = out@aw[:H], e = out@aw[H:] (warp per (b,l)) ----------
__global__ void k_qe(const float* __restrict__ attn_w)
{
    int r    = blockIdx.y;
    int w    = blockIdx.x * 8 + (threadIdx.x >> 5);
    int lane = threadIdx.x & 31;
    const float* o = g_out + ((size_t)r * BL + w) * HDIM;
    float q = 0.f, e = 0.f;
#pragma unroll
    for (int h = lane * 8; h < lane * 8 + 8; h += 4) {
        float4 ov = *(const float4*)&o[h];
        float4 a1 = *(const float4*)&attn_w[h];
        float4 a2 = *(const float4*)&attn_w[HDIM + h];
        q += ov.x*a1.x + ov.y*a1.y + ov.z*a1.z + ov.w*a1.w;
        e += ov.x*a2.x + ov.y*a2.y + ov.z*a2.z + ov.w*a2.w;
    }
#pragma unroll
    for (int off = 16; off; off >>= 1) {
        q += __shfl_down_sync(0xffffffffu, q, off);
        e += __shfl_down_sync(0xffffffffu, e, off);
    }
    if (lane == 0) { g_q[r * BL + w] = q; g_e[r * BL + w] = e; }
}

// ---------------- windowed attention + concat for FC ----------------------
__global__ void k_attn()
{
    int r    = blockIdx.y;
    int bl95 = blockIdx.x;
    int b    = bl95 / MSEQ, l = bl95 % MSEQ;
    int h    = threadIdx.x;

    const float* qrow = g_q + r * BL + b * LSEQ;
    const float* erow = g_e + r * BL + b * LSEQ;
    float qv = qrow[l + WINW];
    float s[WINW];
    float mx = -1e30f;
#pragma unroll
    for (int k = 0; k < WINW; k++) { s[k] = qv + erow[l + k]; mx = fmaxf(mx, s[k]); }
    float sum = 0.f;
#pragma unroll
    for (int k = 0; k < WINW; k++) { s[k] = __expf(s[k] - mx); sum += s[k]; }
    float inv = __fdividef(1.f, sum);

    const float* o = g_out + ((size_t)r * BL + b * LSEQ + l) * HDIM;
    float c = 0.f;
#pragma unroll
    for (int k = 0; k < WINW; k++) c += s[k] * inv * o[k * HDIM + h];

    size_t m = (size_t)r * BM95 + bl95;
    g_cat[m * (2*HDIM) + h]        = c;
    g_cat[m * (2*HDIM) + HDIM + h] = o[WINW * HDIM + h];
}

// ---------------- final head: concat(rnn1[b,l], rnn2[b,min(l+D,99)]) ------
__global__ void k_final(const float* __restrict__ outW, const float* __restrict__ outb,
                        float* __restrict__ out)
{
    int w    = blockIdx.x * 8 + (threadIdx.x >> 5);
    int lane = threadIdx.x & 31;
    int b = w / LSEQ, l = w % LSEQ;

    const float* A1 = (l < WINW)
        ? (g_out   + ((size_t)(b * LSEQ + l)) * HDIM)
        : (g_fused + ((size_t)(b * MSEQ + l - WINW)) * HDIM);
    int lidx = min(l + DSH, LSEQ - 1);
    const float* A2 = (lidx < WINW)
        ? (g_out   + ((size_t)BL + b * LSEQ + lidx) * HDIM)
        : (g_fused + ((size_t)BM95 + b * MSEQ + lidx - WINW) * HDIM);

    float acc = 0.f;
#pragma unroll
    for (int h = lane * 8; h < lane * 8 + 8; h += 4) {
        float4 a  = *(const float4*)&A1[h];
        float4 w1 = *(const float4*)&outW[h];
        acc += a.x*w1.x + a.y*w1.y + a.z*w1.z + a.w*w1.w;
        float4 a2 = *(const float4*)&A2[h];
        float4 w2 = *(const float4*)&outW[HDIM + h];
        acc += a2.x*w2.x + a2.y*w2.y + a2.z*w2.z + a2.w*w2.w;
    }
#pragma unroll
    for (int off = 16; off; off >>= 1)
        acc += __shfl_down_sync(0xffffffffu, acc, off);
    if (lane == 0) out[w] = __fdividef(1.f, 1.f + __expf(-(acc + outb[0])));
}

// ---------------------------------------------------------------------------
extern "C" void kernel_launch(void* const* d_in, const int* in_sizes, int n_in,
                              void* d_out, int out_size)
{
    const float* received = (const float*)d_in[0];
    const float* r1_Wih0  = (const float*)d_in[1];
    const float* r1_Whh0  = (const float*)d_in[2];
    const float* r1_bih0  = (const float*)d_in[3];
    const float* r1_bhh0  = (const float*)d_in[4];
    const float* r1_Wih1  = (const float*)d_in[5];
    const float* r1_Whh1  = (const float*)d_in[6];
    const float* r1_bih1  = (const float*)d_in[7];
    const float* r1_bhh1  = (const float*)d_in[8];
    const float* r2_Wih0  = (const float*)d_in[9];
    const float* r2_Whh0  = (const float*)d_in[10];
    const float* r2_bih0  = (const float*)d_in[11];
    const float* r2_bhh0  = (const float*)d_in[12];
    const float* r2_Wih1  = (const float*)d_in[13];
    const float* r2_Whh1  = (const float*)d_in[14];
    const float* r2_bih1  = (const float*)d_in[15];
    const float* r2_bhh1  = (const float*)d_in[16];
    const float* attn_w   = (const float*)d_in[17];
    const float* fc_W     = (const float*)d_in[18];
    const float* fc_b     = (const float*)d_in[19];
    const float* out_W    = (const float*)d_in[20];
    const float* out_b    = (const float*)d_in[21];
    float* out = (float*)d_out;

    float* d_xw1;   cudaGetSymbolAddress((void**)&d_xw1,   g_xw1);
    float* d_h1;    cudaGetSymbolAddress((void**)&d_h1,    g_h1);
    float* d_gout;  cudaGetSymbolAddress((void**)&d_gout,  g_out);
    float* d_cat;   cudaGetSymbolAddress((void**)&d_cat,   g_cat);
    float* d_fused; cudaGetSymbolAddress((void**)&d_fused, g_fused);

    cudaFuncSetAttribute(k_rec_clu<1>, cudaFuncAttributeMaxDynamicSharedMemorySize, RECC_SMEM);
    cudaFuncSetAttribute(k_rec_clu<0>, cudaFuncAttributeMaxDynamicSharedMemorySize, RECC_SMEM);
    cudaFuncSetAttribute(k_mma,        cudaFuncAttributeMaxDynamicSharedMemorySize, MM_SMEM);

    // 1. convert the four 768x256 recurrent matrices to bf16
    k_prep<<<(4*G3*HDIM + 255)/256, 256>>>(r1_Whh0, r2_Whh0, r1_Whh1, r2_Whh1);
    // 2. layer-0 recurrence (cluster, resident W) with fused input projection
    k_rec_clu<1><<<dim3(64, 2), 512, RECC_SMEM>>>((const float*)0, received,
                                         r1_Wih0, r2_Wih0, r1_bih0, r2_bih0,
                                         0, r1_bhh0, r2_bhh0, d_h1);
    // 3. xw1 = h1 @ Wih1.T + bih1 — Markidis bf16 mma GEMM
    k_mma<<<dim3(G3/128, BL/128, 2), 256, MM_SMEM>>>(
        d_h1, (size_t)BL*HDIM, r1_Wih1, r2_Wih1, r1_bih1, r2_bih1,
        d_xw1, (size_t)BL*G3, G3, HDIM);
    // 4. layer-1 recurrence (cluster, resident W)
    k_rec_clu<0><<<dim3(64, 2), 512, RECC_SMEM>>>(d_xw1, (const float*)0,
                                         (const float*)0, (const float*)0,
                                         (const float*)0, (const float*)0,
                                         2, r1_bhh1, r2_bhh1, d_gout);
    // 5. attention scalars q,e
    k_qe<<<dim3(BL/8, 2), 256>>>(attn_w);
    // 6. windowed softmax attention + concat
    k_attn<<<dim3(BM95, 2), 256>>>();
    // 7. FC — Markidis bf16 mma GEMM
    k_mma<<<dim3(HDIM/128, (2*BM95)/128, 1), 256, MM_SMEM>>>(
        d_cat, 0, fc_W, fc_W, fc_b, fc_b,
        d_fused, 0, HDIM, 2*HDIM);
    // 8. final projection + sigmoid
    k_final<<<BL/8, 256>>>(out_W, out_b, out);
}